// round 4
// baseline (speedup 1.0000x reference)
#include <cuda_runtime.h>
#include <cuda_bf16.h>
#include <cstddef>
#include <math.h>

// Problem constants
#define BB 8
#define CC 256
#define HH 128
#define WW2 128
#define NN 16384           // H*W
#define BN 131072          // B*N
#define QKVC 768           // 3C
#define HC 512             // 2C

// ---------------- scratch (device globals; no allocation) ----------------
__device__ float d_qkv_g[(size_t)BN * QKVC];
__device__ float d_qkv_w[(size_t)BN * QKVC];
__device__ float d_h_g[(size_t)BN * HC];
__device__ float d_h_w[(size_t)BN * HC];
__device__ float d_xvec_g[(size_t)BN * CC / 1 / (BN/ (size_t)BN)]; // B*C*N = 33554432
__device__ float d_xvec_w[33554432];
__device__ float d_xbit_g[BN];
__device__ float d_xbit_w[BN];
__device__ float d_mu[2][BB * HC];
__device__ float d_rstd[2][BB * HC];
__device__ float d_fw[2][HC];
__device__ float d_fb[2];

// ---------------- GEMM: out[r, j] = sum_c x[b, c, n] * W[c, j] (+bias) ----
// r = b*N + n ; A is x^T per batch (K-stride = N, M contiguous).
// 128x128 tile, BK=16, 256 threads, 8x8 microtile.
__global__ __launch_bounds__(256) void sgemm_tok(
    const float* __restrict__ X, const float* __restrict__ W,
    const float* __restrict__ bias, int hasBias, int ncols, int dst)
{
    float* out = (dst == 0) ? d_qkv_g : (dst == 1) ? d_h_g
               : (dst == 2) ? d_qkv_w : d_h_w;

    __shared__ float As[16][128];
    __shared__ float Bs[16][128];

    const int t  = threadIdx.x;
    const int bj = blockIdx.x * 128;
    const int r0 = blockIdx.y * 128;
    const int b  = r0 >> 14;          // r0 / N
    const int n0 = r0 & (NN - 1);

    const float* Ab = X + (size_t)b * CC * NN + n0;

    float acc[8][8];
#pragma unroll
    for (int i = 0; i < 8; i++)
#pragma unroll
        for (int j = 0; j < 8; j++) acc[i][j] = 0.f;

    const int m0 = (t >> 4) << 3;
    const int j0 = (t & 15) << 3;

    for (int c0 = 0; c0 < CC; c0 += 16) {
#pragma unroll
        for (int q = 0; q < 2; q++) {
            int L   = t + q * 256;
            int kk  = L >> 5;
            int off = (L & 31) << 2;
            *(float4*)&As[kk][off] =
                *(const float4*)&Ab[(size_t)(c0 + kk) * NN + off];
            *(float4*)&Bs[kk][off] =
                *(const float4*)&W[(size_t)(c0 + kk) * ncols + bj + off];
        }
        __syncthreads();
#pragma unroll
        for (int kk = 0; kk < 16; kk++) {
            float a[8], bb[8];
            *(float4*)&a[0]  = *(float4*)&As[kk][m0];
            *(float4*)&a[4]  = *(float4*)&As[kk][m0 + 4];
            *(float4*)&bb[0] = *(float4*)&Bs[kk][j0];
            *(float4*)&bb[4] = *(float4*)&Bs[kk][j0 + 4];
#pragma unroll
            for (int i = 0; i < 8; i++)
#pragma unroll
                for (int j = 0; j < 8; j++) acc[i][j] += a[i] * bb[j];
        }
        __syncthreads();
    }

    float bv[8];
#pragma unroll
    for (int j = 0; j < 8; j++) bv[j] = hasBias ? bias[bj + j0 + j] : 0.f;

#pragma unroll
    for (int i = 0; i < 8; i++) {
        float* orow = out + (size_t)(r0 + m0 + i) * ncols + bj + j0;
        float4 v0, v1;
        v0.x = acc[i][0] + bv[0]; v0.y = acc[i][1] + bv[1];
        v0.z = acc[i][2] + bv[2]; v0.w = acc[i][3] + bv[3];
        v1.x = acc[i][4] + bv[4]; v1.y = acc[i][5] + bv[5];
        v1.z = acc[i][6] + bv[6]; v1.w = acc[i][7] + bv[7];
        *(float4*)&orow[0] = v0;
        *(float4*)&orow[4] = v1;
    }
}

// ---------------- windowed attention, one block = (window, head) ----------
// 64 tokens x 64 dims; S=QK^T*scale, softmax (registers+shfl), ctx=PV,
// transposed store into (B, C, H, W) layout via smem.
__global__ __launch_bounds__(256) void attn_kernel(int sel)
{
    const float* qkv = sel ? d_qkv_w : d_qkv_g;
    float* xvec      = sel ? d_xvec_w : d_xvec_g;

    __shared__ float sm[3 * 64 * 64];   // 48 KB
    float* qT = sm;                     // [d][i] then reused for P[i][j]
    float* kT = sm + 4096;              // [d][j] then reused for ctxT[d][i]
    float* vs = sm + 8192;              // [j][d]

    const int t    = threadIdx.x;
    const int bx   = blockIdx.x;
    const int win  = bx >> 2;
    const int head = bx & 3;
    const int b    = win >> 8;
    const int wib  = win & 255;
    const int xw   = wib >> 4;
    const int yw   = wib & 15;

    // ---- load Q (scaled, transposed), K (transposed), V ----
    {
        const int i  = t >> 2;
        const int d0 = (t & 3) << 4;
        const int ni = ((xw << 3) + (i >> 3)) * WW2 + (yw << 3) + (i & 7);
        const float* rp = qkv + (size_t)(b * NN + ni) * QKVC + head * 64;
#pragma unroll
        for (int u = 0; u < 4; u++) {
            int d = d0 + u * 4;
            float4 qv = *(const float4*)&rp[d];
            qT[(d + 0) * 64 + i] = qv.x * 0.125f;
            qT[(d + 1) * 64 + i] = qv.y * 0.125f;
            qT[(d + 2) * 64 + i] = qv.z * 0.125f;
            qT[(d + 3) * 64 + i] = qv.w * 0.125f;
            float4 kv = *(const float4*)&rp[256 + d];
            kT[(d + 0) * 64 + i] = kv.x;
            kT[(d + 1) * 64 + i] = kv.y;
            kT[(d + 2) * 64 + i] = kv.z;
            kT[(d + 3) * 64 + i] = kv.w;
            *(float4*)&vs[i * 64 + d] = *(const float4*)&rp[512 + d];
        }
    }
    __syncthreads();

    const int ig = t >> 4, jg = t & 15;
    const int i0 = ig << 2, j0 = jg << 2;

    // ---- S = Q K^T ----
    float s[4][4];
#pragma unroll
    for (int a = 0; a < 4; a++)
#pragma unroll
        for (int c = 0; c < 4; c++) s[a][c] = 0.f;

#pragma unroll 8
    for (int kk = 0; kk < 64; kk++) {
        float a[4], bb[4];
        *(float4*)a  = *(float4*)&qT[kk * 64 + i0];
        *(float4*)bb = *(float4*)&kT[kk * 64 + j0];
#pragma unroll
        for (int ri = 0; ri < 4; ri++)
#pragma unroll
            for (int rj = 0; rj < 4; rj++) s[ri][rj] += a[ri] * bb[rj];
    }
    __syncthreads();   // all reads of qT/kT done before overwrite

    // ---- softmax over j (row spans 16 lanes of a half-warp) ----
#pragma unroll
    for (int ri = 0; ri < 4; ri++) {
        float m = fmaxf(fmaxf(s[ri][0], s[ri][1]), fmaxf(s[ri][2], s[ri][3]));
#pragma unroll
        for (int off = 8; off > 0; off >>= 1)
            m = fmaxf(m, __shfl_xor_sync(0xffffffffu, m, off));
        float sum = 0.f;
#pragma unroll
        for (int rj = 0; rj < 4; rj++) {
            s[ri][rj] = __expf(s[ri][rj] - m);
            sum += s[ri][rj];
        }
#pragma unroll
        for (int off = 8; off > 0; off >>= 1)
            sum += __shfl_xor_sync(0xffffffffu, sum, off);
        float inv = 1.0f / sum;
#pragma unroll
        for (int rj = 0; rj < 4; rj++) s[ri][rj] *= inv;
    }

    // ---- write P into qT buffer as P[i][j] ----
#pragma unroll
    for (int ri = 0; ri < 4; ri++)
#pragma unroll
        for (int rj = 0; rj < 4; rj++)
            qT[(i0 + ri) * 64 + (j0 + rj)] = s[ri][rj];
    __syncthreads();

    // ---- ctx = P V (d-range reuses jg mapping) ----
    float c4[4][4];
#pragma unroll
    for (int a = 0; a < 4; a++)
#pragma unroll
        for (int c = 0; c < 4; c++) c4[a][c] = 0.f;

#pragma unroll 8
    for (int kk = 0; kk < 64; kk++) {
        float p[4];
#pragma unroll
        for (int ri = 0; ri < 4; ri++) p[ri] = qT[(i0 + ri) * 64 + kk];
        float4 vv = *(float4*)&vs[kk * 64 + j0];
        float vb[4] = {vv.x, vv.y, vv.z, vv.w};
#pragma unroll
        for (int ri = 0; ri < 4; ri++)
#pragma unroll
            for (int rd = 0; rd < 4; rd++) c4[ri][rd] += p[ri] * vb[rd];
    }
    __syncthreads();

    // ---- transpose ctx into kT as ctxT[d][i] ----
#pragma unroll
    for (int ri = 0; ri < 4; ri++)
#pragma unroll
        for (int rd = 0; rd < 4; rd++)
            kT[(j0 + rd) * 64 + (i0 + ri)] = c4[ri][rd];
    __syncthreads();

    // ---- coalesced store to (B, C, H, W) ----
    for (int e = t; e < 4096; e += 256) {
        int d  = e >> 6;
        int ii = e & 63;
        int ni = ((xw << 3) + (ii >> 3)) * WW2 + (yw << 3) + (ii & 7);
        xvec[((size_t)(b * CC + head * 64 + d)) * NN + ni] = kT[d * 64 + ii];
    }
}

// ---------------- fold fc2+bit into a single 2C vector ----------------
__global__ void fuse_fw(const float* __restrict__ fc2w,
                        const float* __restrict__ fc2b,
                        const float* __restrict__ bitw,
                        const float* __restrict__ bitb, int sel)
{
    int k = blockIdx.x * blockDim.x + threadIdx.x;
    if (k < HC) {
        float s = 0.f;
        for (int c = 0; c < CC; c++) s += fc2w[(size_t)k * CC + c] * bitw[c];
        d_fw[sel][k] = s;
    }
    if (k == 0) {
        float s = 0.f;
        for (int c = 0; c < CC; c++) s += fc2b[c] * bitw[c];
        d_fb[sel] = s + bitb[0];
    }
}

// ---------------- InstanceNorm stats over h: per (b, channel) -----------
__global__ __launch_bounds__(256) void inorm_stats(int sel)
{
    const float* h = sel ? d_h_w : d_h_g;
    const int b  = blockIdx.x;
    const int c0 = blockIdx.y * 32;
    const int cl = threadIdx.x & 31;
    const int rr = threadIdx.x >> 5;   // 8 row-lanes

    const float* base = h + (size_t)b * NN * HC + c0 + cl;
    float s = 0.f, s2 = 0.f;
    for (int n = rr; n < NN; n += 8) {
        float v = base[(size_t)n * HC];
        s += v; s2 += v * v;
    }
    __shared__ float ss[8][32], ss2[8][32];
    ss[rr][cl] = s; ss2[rr][cl] = s2;
    __syncthreads();
    if (threadIdx.x < 32) {
        float a = 0.f, a2 = 0.f;
#pragma unroll
        for (int r = 0; r < 8; r++) { a += ss[r][threadIdx.x]; a2 += ss2[r][threadIdx.x]; }
        float m   = a * (1.0f / NN);
        float var = a2 * (1.0f / NN) - m * m;
        d_mu[sel][b * HC + c0 + threadIdx.x]   = m;
        d_rstd[sel][b * HC + c0 + threadIdx.x] = rsqrtf(var + 1e-5f);
    }
}

// ---------------- norm + gelu + fused fc2/bit GEMV -> x_bit ----------------
__global__ __launch_bounds__(256) void mlp_bit(int sel)
{
    const float* h = sel ? d_h_w : d_h_g;
    float* xbit    = sel ? d_xbit_w : d_xbit_g;

    __shared__ float smu[HC], srs[HC], sfw[HC];
    const int t  = threadIdx.x;
    const int r0 = blockIdx.x * 8;
    const int b  = r0 >> 14;

    smu[t]       = d_mu[sel][b * HC + t];
    smu[t + 256] = d_mu[sel][b * HC + t + 256];
    srs[t]       = d_rstd[sel][b * HC + t];
    srs[t + 256] = d_rstd[sel][b * HC + t + 256];
    sfw[t]       = d_fw[sel][t];
    sfw[t + 256] = d_fw[sel][t + 256];
    __syncthreads();

    const float fb = d_fb[sel];
    const int w = t >> 5, lane = t & 31;
    const int r = r0 + w;
    const float* hr = h + (size_t)r * HC;

    float acc = 0.f;
#pragma unroll
    for (int ii = 0; ii < 16; ii++) {
        int k   = lane + (ii << 5);
        float v = (hr[k] - smu[k]) * srs[k];
        float g = 0.5f * v * (1.0f + erff(v * 0.70710678118f));
        acc += g * sfw[k];
    }
#pragma unroll
    for (int off = 16; off > 0; off >>= 1)
        acc += __shfl_xor_sync(0xffffffffu, acc, off);
    if (lane == 0) xbit[r] = fmaxf(acc + fb, 0.0f);
}

// ---------------- final combine ----------------
__global__ __launch_bounds__(256) void combine_kernel(
    const float* __restrict__ x, float* __restrict__ out)
{
    size_t idx = (size_t)blockIdx.x * 256 + threadIdx.x;   // float4 index
    size_t e   = idx * 4;
    int n      = (int)(e & (NN - 1));
    size_t bc  = e >> 14;
    int b      = (int)(bc >> 8);

    float4 x4 = *(const float4*)&x[e];
    float4 vg = *(const float4*)&d_xvec_g[e];
    float4 vw = *(const float4*)&d_xvec_w[e];
    float4 bg = *(const float4*)&d_xbit_g[(size_t)b * NN + n];
    float4 bw = *(const float4*)&d_xbit_w[(size_t)b * NN + n];

    float4 o;
    {
        float wv = bw.x * vw.x; float sg = 1.0f / (1.0f + __expf(-wv));
        o.x = x4.x * sg + (bg.x * vg.x) * (1.0f - sg);
    }
    {
        float wv = bw.y * vw.y; float sg = 1.0f / (1.0f + __expf(-wv));
        o.y = x4.y * sg + (bg.y * vg.y) * (1.0f - sg);
    }
    {
        float wv = bw.z * vw.z; float sg = 1.0f / (1.0f + __expf(-wv));
        o.z = x4.z * sg + (bg.z * vg.z) * (1.0f - sg);
    }
    {
        float wv = bw.w * vw.w; float sg = 1.0f / (1.0f + __expf(-wv));
        o.w = x4.w * sg + (bg.w * vg.w) * (1.0f - sg);
    }
    *(float4*)&out[e] = o;
}

// ---------------- launch ----------------
extern "C" void kernel_launch(void* const* d_in, const int* in_sizes, int n_in,
                              void* d_out, int out_size)
{
    const float* x       = (const float*)d_in[0];
    const float* g_qkv   = (const float*)d_in[1];
    const float* g_fc1_w = (const float*)d_in[2];
    const float* g_fc1_b = (const float*)d_in[3];
    const float* g_fc2_w = (const float*)d_in[4];
    const float* g_fc2_b = (const float*)d_in[5];
    const float* g_bit_w = (const float*)d_in[6];
    const float* g_bit_b = (const float*)d_in[7];
    const float* w_qkv   = (const float*)d_in[8];
    const float* w_fc1_w = (const float*)d_in[9];
    const float* w_fc1_b = (const float*)d_in[10];
    const float* w_fc2_w = (const float*)d_in[11];
    const float* w_fc2_b = (const float*)d_in[12];
    const float* w_bit_w = (const float*)d_in[13];
    const float* w_bit_b = (const float*)d_in[14];
    float* out = (float*)d_out;

    // big token GEMMs
    sgemm_tok<<<dim3(QKVC / 128, BN / 128), 256>>>(x, g_qkv, nullptr, 0, QKVC, 0);
    sgemm_tok<<<dim3(HC / 128, BN / 128),   256>>>(x, g_fc1_w, g_fc1_b, 1, HC, 1);
    sgemm_tok<<<dim3(QKVC / 128, BN / 128), 256>>>(x, w_qkv, nullptr, 0, QKVC, 2);
    sgemm_tok<<<dim3(HC / 128, BN / 128),   256>>>(x, w_fc1_w, w_fc1_b, 1, HC, 3);

    // windowed attention (2048 windows * 4 heads per branch)
    attn_kernel<<<8192, 256>>>(0);
    attn_kernel<<<8192, 256>>>(1);

    // folded fc2+bit weights
    fuse_fw<<<2, 256>>>(g_fc2_w, g_fc2_b, g_bit_w, g_bit_b, 0);
    fuse_fw<<<2, 256>>>(w_fc2_w, w_fc2_b, w_bit_w, w_bit_b, 1);

    // instance-norm stats + bit branch
    inorm_stats<<<dim3(BB, 16), 256>>>(0);
    inorm_stats<<<dim3(BB, 16), 256>>>(1);
    mlp_bit<<<BN / 8, 256>>>(0);
    mlp_bit<<<BN / 8, 256>>>(1);

    // final blend
    combine_kernel<<<(33554432 / 4) / 256, 256>>>(x, out);
}

// round 8
// speedup vs baseline: 1.5072x; 1.5072x over previous
#include <cuda_runtime.h>
#include <cuda_bf16.h>
#include <mma.h>
#include <cstddef>
#include <cstdint>
#include <math.h>

using namespace nvcuda;

// Problem constants
#define BB 8
#define CC 256
#define HH 128
#define WW2 128
#define NN 16384           // H*W
#define BN 131072          // B*N
#define QKVC 768           // 3C
#define HC 512             // 2C
#define OSTR 2560          // fused GEMM output columns: g_qkv|g_fc1|w_qkv|w_fc1

// column offsets inside the fused output  [gqkv 0..768 | gh 768..1280 | wqkv 1280..2048 | wh 2048..2560]
#define OFF_GQKV 0
#define OFF_GH   768
#define OFF_WQKV 1280
#define OFF_WH   2048

// ---------------- scratch (device globals; no allocation) ----------------
__device__ float d_big[(size_t)BN * OSTR];   // fused GEMM output (1.34 GB)
__device__ __nv_bfloat16 d_xhi[(size_t)BB * CC * NN];
__device__ __nv_bfloat16 d_xlo[(size_t)BB * CC * NN];
__device__ __nv_bfloat16 d_whi[(size_t)CC * OSTR];
__device__ __nv_bfloat16 d_wlo[(size_t)CC * OSTR];
__device__ float d_xvec_g[(size_t)BB * CC * NN];
__device__ float d_xvec_w[(size_t)BB * CC * NN];
__device__ float d_xbit_g[BN];
__device__ float d_xbit_w[BN];
__device__ float d_mu[2][BB * HC];
__device__ float d_rstd[2][BB * HC];
__device__ float d_fw[2][HC];
__device__ float d_fb[2];

// ======================= helpers ============================
__device__ __forceinline__ uint32_t smem_u32(const void* p) {
    uint32_t a;
    asm("{ .reg .u64 t; cvta.to.shared.u64 t, %1; cvt.u32.u64 %0, t; }"
        : "=r"(a) : "l"(p));
    return a;
}
__device__ __forceinline__ void cp16(uint32_t dst, const void* src) {
    asm volatile("cp.async.cg.shared.global [%0], [%1], 16;"
                 :: "r"(dst), "l"(src));
}
__device__ __forceinline__ void split_bf16(float v, __nv_bfloat16& hi, __nv_bfloat16& lo) {
    hi = __float2bfloat16(v);
    lo = __float2bfloat16(v - __bfloat162float(hi));
}

// ================== split x -> (hi, lo) bf16, same layout ==================
__global__ __launch_bounds__(256) void split_x(const float* __restrict__ x)
{
    size_t i = ((size_t)blockIdx.x * 256 + threadIdx.x) * 4;
    float4 v = *(const float4*)&x[i];
    __nv_bfloat16 h[4], l[4];
    split_bf16(v.x, h[0], l[0]);
    split_bf16(v.y, h[1], l[1]);
    split_bf16(v.z, h[2], l[2]);
    split_bf16(v.w, h[3], l[3]);
    *(uint2*)&d_xhi[i] = *(uint2*)h;
    *(uint2*)&d_xlo[i] = *(uint2*)l;
}

// ====== pack weights into [c][2560] bf16 hi/lo (fused column space) ========
__global__ __launch_bounds__(256) void pack_w(
    const float* __restrict__ gq, const float* __restrict__ gf,
    const float* __restrict__ wq, const float* __restrict__ wf)
{
    int idx = blockIdx.x * 256 + threadIdx.x;   // 0 .. CC*OSTR-1
    int c = idx / OSTR;
    int j = idx % OSTR;
    const float* src; int jj; int ncol;
    if (j < 768)       { src = gq; jj = j;        ncol = QKVC; }
    else if (j < 1280) { src = gf; jj = j - 768;  ncol = HC;   }
    else if (j < 2048) { src = wq; jj = j - 1280; ncol = QKVC; }
    else               { src = wf; jj = j - 2048; ncol = HC;   }
    float v = src[(size_t)c * ncol + jj];
    __nv_bfloat16 h, l;
    split_bf16(v, h, l);
    d_whi[idx] = h;
    d_wlo[idx] = l;
}

// ============== WMMA bf16x3 GEMM: d_big = A @ W (fp32-accurate) ============
// A = x per batch [C][N] -> col-major (M=token, K=channel). B = packed [C][2560].
// a = ahi + alo, b = bhi + blo; acc += ahi*bhi + ahi*blo + alo*bhi.
// Tile BM=128, BN=128, BK=32; 8 warps, warp tile 64x32, m16n16k16 bf16.

#define BKT 32
#define LDB 136                 // bf16 elements per smem row (272B, 16B mult)
#define MATB (BKT * LDB)        // 4352 bf16 per matrix per stage
#define STG_ELEM (4 * MATB)     // Ahi|Alo|Bhi|Blo = 17408 bf16 = 34816 B
#define GEMM_SMEM (2 * STG_ELEM * 2)

__global__ __launch_bounds__(256, 1) void gemm_bf16x3()
{
    extern __shared__ __nv_bfloat16 sm[];
    const uint32_t smb = smem_u32(sm);
    const int t   = threadIdx.x;
    const int wid = t >> 5;

    const int nt = blockIdx.x;          // 0..19
    const int mt = blockIdx.y;          // 0..1023
    const int j0 = nt * 128;
    const int r0 = mt * 128;
    const int b  = mt >> 7;
    const int n0 = r0 & (NN - 1);

    const __nv_bfloat16* axhi = d_xhi + (size_t)b * CC * NN + n0;
    const __nv_bfloat16* axlo = d_xlo + (size_t)b * CC * NN + n0;
    const __nv_bfloat16* bwhi = d_whi + j0;
    const __nv_bfloat16* bwlo = d_wlo + j0;

    const int wm = (wid & 1) * 64;      // 2 M positions x 64
    const int wn = (wid >> 1) * 32;     // 4 N positions x 32

    wmma::fragment<wmma::accumulator, 16, 16, 16, float> acc[4][2];
#pragma unroll
    for (int i = 0; i < 4; i++)
#pragma unroll
        for (int j = 0; j < 2; j++) wmma::fill_fragment(acc[i][j], 0.0f);

    // stage loader: 2048 16B chunks (512 per matrix), 256 thr x 8
    auto load_stage = [&](int s, int c0) {
        const uint32_t sbase = smb + (uint32_t)(s * STG_ELEM) * 2;
#pragma unroll
        for (int i = 0; i < 8; i++) {
            int q    = t + i * 256;
            int mat  = q >> 9;
            int w    = q & 511;
            int k    = w >> 4;
            int c8   = (w & 15) << 3;      // bf16 element offset, 16B chunks
            uint32_t dst = sbase + (uint32_t)(mat * MATB + k * LDB + c8) * 2;
            const __nv_bfloat16* src;
            if (mat == 0)      src = axhi + (size_t)(c0 + k) * NN + c8;
            else if (mat == 1) src = axlo + (size_t)(c0 + k) * NN + c8;
            else if (mat == 2) src = bwhi + (size_t)(c0 + k) * OSTR + c8;
            else               src = bwlo + (size_t)(c0 + k) * OSTR + c8;
            cp16(dst, src);
        }
        asm volatile("cp.async.commit_group;");
    };

    load_stage(0, 0);

#pragma unroll 1
    for (int kt = 0; kt < 8; kt++) {
        if (kt + 1 < 8) {
            load_stage((kt + 1) & 1, (kt + 1) * BKT);
            asm volatile("cp.async.wait_group 1;");
        } else {
            asm volatile("cp.async.wait_group 0;");
        }
        __syncthreads();

        const __nv_bfloat16* st  = sm + (size_t)(kt & 1) * STG_ELEM;
        const __nv_bfloat16* Ah  = st;
        const __nv_bfloat16* Al  = st + MATB;
        const __nv_bfloat16* Bh  = st + 2 * MATB;
        const __nv_bfloat16* Bl  = st + 3 * MATB;

#pragma unroll
        for (int ks = 0; ks < 2; ks++) {
            wmma::fragment<wmma::matrix_a, 16, 16, 16, __nv_bfloat16,
                           wmma::col_major> ah[4], al[4];
            wmma::fragment<wmma::matrix_b, 16, 16, 16, __nv_bfloat16,
                           wmma::row_major> bh[2], bl[2];
#pragma unroll
            for (int i = 0; i < 4; i++) {
                wmma::load_matrix_sync(ah[i], Ah + (ks * 16) * LDB + wm + i * 16, LDB);
                wmma::load_matrix_sync(al[i], Al + (ks * 16) * LDB + wm + i * 16, LDB);
            }
#pragma unroll
            for (int j = 0; j < 2; j++) {
                wmma::load_matrix_sync(bh[j], Bh + (ks * 16) * LDB + wn + j * 16, LDB);
                wmma::load_matrix_sync(bl[j], Bl + (ks * 16) * LDB + wn + j * 16, LDB);
            }
#pragma unroll
            for (int i = 0; i < 4; i++)
#pragma unroll
                for (int j = 0; j < 2; j++) {
                    wmma::mma_sync(acc[i][j], ah[i], bh[j], acc[i][j]);
                    wmma::mma_sync(acc[i][j], ah[i], bl[j], acc[i][j]);
                    wmma::mma_sync(acc[i][j], al[i], bh[j], acc[i][j]);
                }
        }
        __syncthreads();
    }

#pragma unroll
    for (int i = 0; i < 4; i++)
#pragma unroll
        for (int j = 0; j < 2; j++)
            wmma::store_matrix_sync(
                d_big + (size_t)(r0 + wm + i * 16) * OSTR + j0 + wn + j * 16,
                acc[i][j], OSTR, wmma::mem_row_major);
}

// ---------------- windowed attention, one block = (window, head) ----------
__global__ __launch_bounds__(256) void attn_kernel(int sel)
{
    const int qoff = sel ? OFF_WQKV : OFF_GQKV;
    float* xvec    = sel ? d_xvec_w : d_xvec_g;

    __shared__ float sm[3 * 64 * 64];   // 48 KB
    float* qT = sm;
    float* kT = sm + 4096;
    float* vs = sm + 8192;

    const int t    = threadIdx.x;
    const int bx   = blockIdx.x;
    const int win  = bx >> 2;
    const int head = bx & 3;
    const int b    = win >> 8;
    const int wib  = win & 255;
    const int xw   = wib >> 4;
    const int yw   = wib & 15;

    {
        const int i  = t >> 2;
        const int d0 = (t & 3) << 4;
        const int ni = ((xw << 3) + (i >> 3)) * WW2 + (yw << 3) + (i & 7);
        const float* rp = d_big + (size_t)(b * NN + ni) * OSTR + qoff + head * 64;
#pragma unroll
        for (int u = 0; u < 4; u++) {
            int d = d0 + u * 4;
            float4 qv = *(const float4*)&rp[d];
            qT[(d + 0) * 64 + i] = qv.x * 0.125f;
            qT[(d + 1) * 64 + i] = qv.y * 0.125f;
            qT[(d + 2) * 64 + i] = qv.z * 0.125f;
            qT[(d + 3) * 64 + i] = qv.w * 0.125f;
            float4 kv = *(const float4*)&rp[256 + d];
            kT[(d + 0) * 64 + i] = kv.x;
            kT[(d + 1) * 64 + i] = kv.y;
            kT[(d + 2) * 64 + i] = kv.z;
            kT[(d + 3) * 64 + i] = kv.w;
            *(float4*)&vs[i * 64 + d] = *(const float4*)&rp[512 + d];
        }
    }
    __syncthreads();

    const int ig = t >> 4, jg = t & 15;
    const int i0 = ig << 2, j0 = jg << 2;

    float s[4][4];
#pragma unroll
    for (int a = 0; a < 4; a++)
#pragma unroll
        for (int c = 0; c < 4; c++) s[a][c] = 0.f;

#pragma unroll 8
    for (int kk = 0; kk < 64; kk++) {
        float a[4], bb[4];
        *(float4*)a  = *(float4*)&qT[kk * 64 + i0];
        *(float4*)bb = *(float4*)&kT[kk * 64 + j0];
#pragma unroll
        for (int ri = 0; ri < 4; ri++)
#pragma unroll
            for (int rj = 0; rj < 4; rj++) s[ri][rj] += a[ri] * bb[rj];
    }
    __syncthreads();

#pragma unroll
    for (int ri = 0; ri < 4; ri++) {
        float m = fmaxf(fmaxf(s[ri][0], s[ri][1]), fmaxf(s[ri][2], s[ri][3]));
#pragma unroll
        for (int off = 8; off > 0; off >>= 1)
            m = fmaxf(m, __shfl_xor_sync(0xffffffffu, m, off));
        float sum = 0.f;
#pragma unroll
        for (int rj = 0; rj < 4; rj++) {
            s[ri][rj] = __expf(s[ri][rj] - m);
            sum += s[ri][rj];
        }
#pragma unroll
        for (int off = 8; off > 0; off >>= 1)
            sum += __shfl_xor_sync(0xffffffffu, sum, off);
        float inv = 1.0f / sum;
#pragma unroll
        for (int rj = 0; rj < 4; rj++) s[ri][rj] *= inv;
    }

#pragma unroll
    for (int ri = 0; ri < 4; ri++)
#pragma unroll
        for (int rj = 0; rj < 4; rj++)
            qT[(i0 + ri) * 64 + (j0 + rj)] = s[ri][rj];
    __syncthreads();

    float c4[4][4];
#pragma unroll
    for (int a = 0; a < 4; a++)
#pragma unroll
        for (int c = 0; c < 4; c++) c4[a][c] = 0.f;

#pragma unroll 8
    for (int kk = 0; kk < 64; kk++) {
        float p[4];
#pragma unroll
        for (int ri = 0; ri < 4; ri++) p[ri] = qT[(i0 + ri) * 64 + kk];
        float4 vv = *(float4*)&vs[kk * 64 + j0];
        float vb[4] = {vv.x, vv.y, vv.z, vv.w};
#pragma unroll
        for (int ri = 0; ri < 4; ri++)
#pragma unroll
            for (int rd = 0; rd < 4; rd++) c4[ri][rd] += p[ri] * vb[rd];
    }
    __syncthreads();

#pragma unroll
    for (int ri = 0; ri < 4; ri++)
#pragma unroll
        for (int rd = 0; rd < 4; rd++)
            kT[(j0 + rd) * 64 + (i0 + ri)] = c4[ri][rd];
    __syncthreads();

    for (int e = t; e < 4096; e += 256) {
        int d  = e >> 6;
        int ii = e & 63;
        int ni = ((xw << 3) + (ii >> 3)) * WW2 + (yw << 3) + (ii & 7);
        xvec[((size_t)(b * CC + head * 64 + d)) * NN + ni] = kT[d * 64 + ii];
    }
}

// ---------------- fold fc2+bit into a single 2C vector ----------------
__global__ void fuse_fw(const float* __restrict__ fc2w,
                        const float* __restrict__ fc2b,
                        const float* __restrict__ bitw,
                        const float* __restrict__ bitb, int sel)
{
    int k = blockIdx.x * blockDim.x + threadIdx.x;
    if (k < HC) {
        float s = 0.f;
        for (int c = 0; c < CC; c++) s += fc2w[(size_t)k * CC + c] * bitw[c];
        d_fw[sel][k] = s;
    }
    if (k == 0) {
        float s = 0.f;
        for (int c = 0; c < CC; c++) s += fc2b[c] * bitw[c];
        d_fb[sel] = s + bitb[0];
    }
}

// ---------------- InstanceNorm stats over h (fc1 bias cancels) -----------
__global__ __launch_bounds__(256) void inorm_stats(int sel)
{
    const int hoff = sel ? OFF_WH : OFF_GH;
    const int b  = blockIdx.x;
    const int c0 = blockIdx.y * 32;
    const int cl = threadIdx.x & 31;
    const int rr = threadIdx.x >> 5;

    const float* base = d_big + (size_t)b * NN * OSTR + hoff + c0 + cl;
    float s = 0.f, s2 = 0.f;
    for (int n = rr; n < NN; n += 8) {
        float v = base[(size_t)n * OSTR];
        s += v; s2 += v * v;
    }
    __shared__ float ss[8][32], ss2[8][32];
    ss[rr][cl] = s; ss2[rr][cl] = s2;
    __syncthreads();
    if (threadIdx.x < 32) {
        float a = 0.f, a2 = 0.f;
#pragma unroll
        for (int r = 0; r < 8; r++) { a += ss[r][threadIdx.x]; a2 += ss2[r][threadIdx.x]; }
        float m   = a * (1.0f / NN);
        float var = a2 * (1.0f / NN) - m * m;
        d_mu[sel][b * HC + c0 + threadIdx.x]   = m;
        d_rstd[sel][b * HC + c0 + threadIdx.x] = rsqrtf(var + 1e-5f);
    }
}

// ---------------- norm + gelu + fused fc2/bit GEMV -> x_bit ----------------
__global__ __launch_bounds__(256) void mlp_bit(int sel)
{
    const int hoff = sel ? OFF_WH : OFF_GH;
    float* xbit    = sel ? d_xbit_w : d_xbit_g;

    __shared__ float smu[HC], srs[HC], sfw[HC];
    const int t  = threadIdx.x;
    const int r0 = blockIdx.x * 8;
    const int b  = r0 >> 14;

    smu[t]       = d_mu[sel][b * HC + t];
    smu[t + 256] = d_mu[sel][b * HC + t + 256];
    srs[t]       = d_rstd[sel][b * HC + t];
    srs[t + 256] = d_rstd[sel][b * HC + t + 256];
    sfw[t]       = d_fw[sel][t];
    sfw[t + 256] = d_fw[sel][t + 256];
    __syncthreads();

    const float fb = d_fb[sel];
    const int w = t >> 5, lane = t & 31;
    const int r = r0 + w;
    const float* hr = d_big + (size_t)r * OSTR + hoff;

    float acc = 0.f;
#pragma unroll
    for (int ii = 0; ii < 16; ii++) {
        int k   = lane + (ii << 5);
        float v = (hr[k] - smu[k]) * srs[k];
        float g = 0.5f * v * (1.0f + erff(v * 0.70710678118f));
        acc += g * sfw[k];
    }
#pragma unroll
    for (int off = 16; off > 0; off >>= 1)
        acc += __shfl_xor_sync(0xffffffffu, acc, off);
    if (lane == 0) xbit[r] = fmaxf(acc + fb, 0.0f);
}

// ---------------- final combine ----------------
__global__ __launch_bounds__(256) void combine_kernel(
    const float* __restrict__ x, float* __restrict__ out)
{
    size_t idx = (size_t)blockIdx.x * 256 + threadIdx.x;
    size_t e   = idx * 4;
    int n      = (int)(e & (NN - 1));
    size_t bc  = e >> 14;
    int b      = (int)(bc >> 8);

    float4 x4 = *(const float4*)&x[e];
    float4 vg = *(const float4*)&d_xvec_g[e];
    float4 vw = *(const float4*)&d_xvec_w[e];
    float4 bg = *(const float4*)&d_xbit_g[(size_t)b * NN + n];
    float4 bw = *(const float4*)&d_xbit_w[(size_t)b * NN + n];

    float4 o;
    {
        float wv = bw.x * vw.x; float sg = 1.0f / (1.0f + __expf(-wv));
        o.x = x4.x * sg + (bg.x * vg.x) * (1.0f - sg);
    }
    {
        float wv = bw.y * vw.y; float sg = 1.0f / (1.0f + __expf(-wv));
        o.y = x4.y * sg + (bg.y * vg.y) * (1.0f - sg);
    }
    {
        float wv = bw.z * vw.z; float sg = 1.0f / (1.0f + __expf(-wv));
        o.z = x4.z * sg + (bg.z * vg.z) * (1.0f - sg);
    }
    {
        float wv = bw.w * vw.w; float sg = 1.0f / (1.0f + __expf(-wv));
        o.w = x4.w * sg + (bg.w * vg.w) * (1.0f - sg);
    }
    *(float4*)&out[e] = o;
}

// ---------------- launch ----------------
extern "C" void kernel_launch(void* const* d_in, const int* in_sizes, int n_in,
                              void* d_out, int out_size)
{
    const float* x       = (const float*)d_in[0];
    const float* g_qkv   = (const float*)d_in[1];
    const float* g_fc1_w = (const float*)d_in[2];
    // d_in[3] = g_fc1_b  (provably cancelled by instance norm)
    const float* g_fc2_w = (const float*)d_in[4];
    const float* g_fc2_b = (const float*)d_in[5];
    const float* g_bit_w = (const float*)d_in[6];
    const float* g_bit_b = (const float*)d_in[7];
    const float* w_qkv   = (const float*)d_in[8];
    const float* w_fc1_w = (const float*)d_in[9];
    // d_in[10] = w_fc1_b (cancelled)
    const float* w_fc2_w = (const float*)d_in[11];
    const float* w_fc2_b = (const float*)d_in[12];
    const float* w_bit_w = (const float*)d_in[13];
    const float* w_bit_b = (const float*)d_in[14];
    float* out = (float*)d_out;

    cudaFuncSetAttribute(gemm_bf16x3, cudaFuncAttributeMaxDynamicSharedMemorySize,
                         GEMM_SMEM);

    // prep: bf16 hi/lo splits of activations + packed weights
    split_x<<<((size_t)BB * CC * NN / 4) / 256, 256>>>(x);
    pack_w<<<(CC * OSTR) / 256, 256>>>(g_qkv, g_fc1_w, w_qkv, w_fc1_w);

    // one fused tensor-core GEMM (bf16x3 == fp32-grade): [BN,256] @ [256,2560]
    gemm_bf16x3<<<dim3(OSTR / 128, BN / 128), 256, GEMM_SMEM>>>();

    // windowed attention (2048 windows * 4 heads per branch)
    attn_kernel<<<8192, 256>>>(0);
    attn_kernel<<<8192, 256>>>(1);

    // folded fc2+bit weights
    fuse_fw<<<2, 256>>>(g_fc2_w, g_fc2_b, g_bit_w, g_bit_b, 0);
    fuse_fw<<<2, 256>>>(w_fc2_w, w_fc2_b, w_bit_w, w_bit_b, 1);

    // instance-norm stats + bit branch
    inorm_stats<<<dim3(BB, 16), 256>>>(0);
    inorm_stats<<<dim3(BB, 16), 256>>>(1);
    mlp_bit<<<BN / 8, 256>>>(0);
    mlp_bit<<<BN / 8, 256>>>(1);

    // final blend
    combine_kernel<<<((size_t)BB * CC * NN / 4) / 256, 256>>>(x, out);
}

// round 10
// speedup vs baseline: 2.5050x; 1.6620x over previous
#include <cuda_runtime.h>
#include <cuda_fp16.h>
#include <cuda_bf16.h>
#include <mma.h>
#include <cstddef>
#include <cstdint>
#include <math.h>

using namespace nvcuda;

// Problem constants
#define BB 8
#define CC 256
#define HH 128
#define WW2 128
#define NN 16384           // H*W
#define BN 131072          // B*N
#define QKVC 768           // 3C
#define HC 512             // 2C
#define OSTR 2560          // fused GEMM output columns: g_qkv|g_fc1|w_qkv|w_fc1

// column offsets inside the fused output  [gqkv 0..768 | gh 768..1280 | wqkv 1280..2048 | wh 2048..2560]
#define OFF_GQKV 0
#define OFF_GH   768
#define OFF_WQKV 1280
#define OFF_WH   2048

// ---------------- scratch (device globals; no allocation) ----------------
__device__ float d_big[(size_t)BN * OSTR];   // fused GEMM output (1.34 GB)
__device__ __half d_xh[(size_t)BB * CC * NN];
__device__ __half d_wh[(size_t)CC * OSTR];
__device__ float d_xvec_g[(size_t)BB * CC * NN];
__device__ float d_xvec_w[(size_t)BB * CC * NN];
__device__ float d_xbit_g[BN];
__device__ float d_xbit_w[BN];
__device__ float d_mu[2][BB * HC];
__device__ float d_rstd[2][BB * HC];
__device__ float d_fw[2][HC];
__device__ float d_fb[2];

// ======================= helpers ============================
__device__ __forceinline__ uint32_t smem_u32(const void* p) {
    uint32_t a;
    asm("{ .reg .u64 t; cvta.to.shared.u64 t, %1; cvt.u32.u64 %0, t; }"
        : "=r"(a) : "l"(p));
    return a;
}
__device__ __forceinline__ void cp16(uint32_t dst, const void* src) {
    asm volatile("cp.async.cg.shared.global [%0], [%1], 16;"
                 :: "r"(dst), "l"(src));
}

// ================== convert x -> fp16, same layout ==================
__global__ __launch_bounds__(256) void split_x(const float* __restrict__ x)
{
    size_t i = ((size_t)blockIdx.x * 256 + threadIdx.x) * 4;
    float4 v = *(const float4*)&x[i];
    __half h[4];
    h[0] = __float2half_rn(v.x);
    h[1] = __float2half_rn(v.y);
    h[2] = __float2half_rn(v.z);
    h[3] = __float2half_rn(v.w);
    *(uint2*)&d_xh[i] = *(uint2*)h;
}

// ====== pack weights into [c][2560] fp16 (fused column space) ========
__global__ __launch_bounds__(256) void pack_w(
    const float* __restrict__ gq, const float* __restrict__ gf,
    const float* __restrict__ wq, const float* __restrict__ wf)
{
    int idx = blockIdx.x * 256 + threadIdx.x;   // 0 .. CC*OSTR-1
    int c = idx / OSTR;
    int j = idx % OSTR;
    const float* src; int jj; int ncol;
    if (j < 768)       { src = gq; jj = j;        ncol = QKVC; }
    else if (j < 1280) { src = gf; jj = j - 768;  ncol = HC;   }
    else if (j < 2048) { src = wq; jj = j - 1280; ncol = QKVC; }
    else               { src = wf; jj = j - 2048; ncol = HC;   }
    d_wh[idx] = __float2half_rn(src[(size_t)c * ncol + jj]);
}

// ============== WMMA fp16 GEMM: d_big = A @ W (fp32 accum) ============
// A = x per batch [C][N] -> col-major (M=token, K=channel). B = packed [C][2560].
// Tile BM=128, BN=256, BK=32; 16 warps, warp tile 32x64, m16n16k16 fp16.

#define BKT 32
#define LDAs 136                // halves per A k-row (128 + 8 pad)
#define LDBs 264                // halves per B k-row (256 + 8 pad)
#define ASTG (BKT * LDAs)       // 4352 halves
#define BSTG (BKT * LDBs)       // 8448 halves
#define STGE (ASTG + BSTG)      // 12800 halves
#define NSTG 3
#define GEMM_SMEM (NSTG * STGE * 2)   // 76800 B

__global__ __launch_bounds__(512, 1) void gemm_f16()
{
    extern __shared__ __half sm[];
    const uint32_t smb = smem_u32(sm);
    const int t   = threadIdx.x;
    const int wid = t >> 5;

    const int nt = blockIdx.x;          // 0..9
    const int mt = blockIdx.y;          // 0..1023
    const int j0 = nt * 256;
    const int r0 = mt * 128;
    const int b  = mt >> 7;
    const int n0 = r0 & (NN - 1);

    const __half* ax = d_xh + (size_t)b * CC * NN + n0;
    const __half* bw = d_wh + j0;

    const int wm = (wid & 3) * 32;      // 4 M positions
    const int wn = (wid >> 2) * 64;     // 4 N positions

    wmma::fragment<wmma::accumulator, 16, 16, 16, float> acc[2][4];
#pragma unroll
    for (int i = 0; i < 2; i++)
#pragma unroll
        for (int j = 0; j < 4; j++) wmma::fill_fragment(acc[i][j], 0.0f);

    // stage loader: A 512 chunks + B 1024 chunks of 16B; 512 thr x 3
    auto load_stage = [&](int s, int c0) {
        const uint32_t sbase = smb + (uint32_t)(s * STGE) * 2;
#pragma unroll
        for (int i = 0; i < 3; i++) {
            int q = t + i * 512;
            if (q < 512) {
                int k = q >> 4, c8 = (q & 15) << 3;
                cp16(sbase + (uint32_t)(k * LDAs + c8) * 2,
                     ax + (size_t)(c0 + k) * NN + c8);
            } else {
                int q2 = q - 512;
                int k = q2 >> 5, j8 = (q2 & 31) << 3;
                cp16(sbase + (uint32_t)(ASTG + k * LDBs + j8) * 2,
                     bw + (size_t)(c0 + k) * OSTR + j8);
            }
        }
        asm volatile("cp.async.commit_group;");
    };

    load_stage(0, 0);
    load_stage(1, BKT);

#pragma unroll 1
    for (int kt = 0; kt < 8; kt++) {
        if (kt + 2 < 8) {
            load_stage((kt + 2) % 3, (kt + 2) * BKT);
            asm volatile("cp.async.wait_group 2;");
        } else if (kt + 1 < 8) {
            asm volatile("cp.async.wait_group 1;");
        } else {
            asm volatile("cp.async.wait_group 0;");
        }
        __syncthreads();

        const __half* st = sm + (size_t)(kt % 3) * STGE;
        const __half* As = st;
        const __half* Bs = st + ASTG;

#pragma unroll
        for (int ks = 0; ks < 2; ks++) {
            wmma::fragment<wmma::matrix_a, 16, 16, 16, __half,
                           wmma::col_major> af[2];
            wmma::load_matrix_sync(af[0], As + (ks * 16) * LDAs + wm, LDAs);
            wmma::load_matrix_sync(af[1], As + (ks * 16) * LDAs + wm + 16, LDAs);
#pragma unroll
            for (int j = 0; j < 4; j++) {
                wmma::fragment<wmma::matrix_b, 16, 16, 16, __half,
                               wmma::row_major> bf;
                wmma::load_matrix_sync(bf, Bs + (ks * 16) * LDBs + wn + j * 16, LDBs);
                wmma::mma_sync(acc[0][j], af[0], bf, acc[0][j]);
                wmma::mma_sync(acc[1][j], af[1], bf, acc[1][j]);
            }
        }
        __syncthreads();
    }

#pragma unroll
    for (int i = 0; i < 2; i++)
#pragma unroll
        for (int j = 0; j < 4; j++)
            wmma::store_matrix_sync(
                d_big + (size_t)(r0 + wm + i * 16) * OSTR + j0 + wn + j * 16,
                acc[i][j], OSTR, wmma::mem_row_major);
}

// ---------------- windowed attention, one block = (window, head) ----------
// P and ctx^T use a 16B-granule XOR swizzle to kill transposed-store conflicts.
__global__ __launch_bounds__(256) void attn_kernel(int sel)
{
    const int qoff = sel ? OFF_WQKV : OFF_GQKV;
    float* xvec    = sel ? d_xvec_w : d_xvec_g;

    __shared__ float sm[3 * 64 * 64];   // 48 KB
    float* qT = sm;                     // Q^T[d][i], then swizzled P^T[j][i]
    float* kT = sm + 4096;              // K^T[d][i], then swizzled ctx^T[d][i]
    float* vs = sm + 8192;              // V[j][d]

    const int t    = threadIdx.x;
    const int bx   = blockIdx.x;
    const int win  = bx >> 2;
    const int head = bx & 3;
    const int b    = win >> 8;
    const int wib  = win & 255;
    const int xw   = wib >> 4;
    const int yw   = wib & 15;

    {
        const int i  = t >> 2;
        const int d0 = (t & 3) << 4;
        const int ni = ((xw << 3) + (i >> 3)) * WW2 + (yw << 3) + (i & 7);
        const float* rp = d_big + (size_t)(b * NN + ni) * OSTR + qoff + head * 64;
#pragma unroll
        for (int u = 0; u < 4; u++) {
            int d = d0 + u * 4;
            float4 qv = *(const float4*)&rp[d];
            qT[(d + 0) * 64 + i] = qv.x * 0.125f;
            qT[(d + 1) * 64 + i] = qv.y * 0.125f;
            qT[(d + 2) * 64 + i] = qv.z * 0.125f;
            qT[(d + 3) * 64 + i] = qv.w * 0.125f;
            float4 kv = *(const float4*)&rp[256 + d];
            kT[(d + 0) * 64 + i] = kv.x;
            kT[(d + 1) * 64 + i] = kv.y;
            kT[(d + 2) * 64 + i] = kv.z;
            kT[(d + 3) * 64 + i] = kv.w;
            *(float4*)&vs[i * 64 + d] = *(const float4*)&rp[512 + d];
        }
    }
    __syncthreads();

    const int ig = t >> 4, jg = t & 15;
    const int i0 = ig << 2, j0 = jg << 2;
    const int ic4 = i0 >> 2;            // 16B-granule index of this thread's i

    // ---- S = Q K^T ----
    float s[4][4];
#pragma unroll
    for (int a = 0; a < 4; a++)
#pragma unroll
        for (int c = 0; c < 4; c++) s[a][c] = 0.f;

#pragma unroll 8
    for (int kk = 0; kk < 64; kk++) {
        float a[4], bb[4];
        *(float4*)a  = *(float4*)&qT[kk * 64 + i0];
        *(float4*)bb = *(float4*)&kT[kk * 64 + j0];
#pragma unroll
        for (int ri = 0; ri < 4; ri++)
#pragma unroll
            for (int rj = 0; rj < 4; rj++) s[ri][rj] += a[ri] * bb[rj];
    }
    __syncthreads();

    // ---- softmax over j ----
#pragma unroll
    for (int ri = 0; ri < 4; ri++) {
        float m = fmaxf(fmaxf(s[ri][0], s[ri][1]), fmaxf(s[ri][2], s[ri][3]));
#pragma unroll
        for (int off = 8; off > 0; off >>= 1)
            m = fmaxf(m, __shfl_xor_sync(0xffffffffu, m, off));
        float sum = 0.f;
#pragma unroll
        for (int rj = 0; rj < 4; rj++) {
            s[ri][rj] = __expf(s[ri][rj] - m);
            sum += s[ri][rj];
        }
#pragma unroll
        for (int off = 8; off > 0; off >>= 1)
            sum += __shfl_xor_sync(0xffffffffu, sum, off);
        float inv = 1.0f / sum;
#pragma unroll
        for (int rj = 0; rj < 4; rj++) s[ri][rj] *= inv;
    }

    // ---- write swizzled P^T[j][i]: addr = j*64 + ((ic4 ^ (j&15))<<2) + ri ----
#pragma unroll
    for (int rj = 0; rj < 4; rj++) {
        int j = j0 + rj;
        int base = j * 64 + (((ic4 ^ (j & 15)) << 2));
#pragma unroll
        for (int ri = 0; ri < 4; ri++)
            qT[base + ri] = s[ri][rj];
    }
    __syncthreads();

    // ---- ctx = P V : read P^T rows as float4 ----
    float c4[4][4];
#pragma unroll
    for (int a = 0; a < 4; a++)
#pragma unroll
        for (int c = 0; c < 4; c++) c4[a][c] = 0.f;

#pragma unroll 8
    for (int kk = 0; kk < 64; kk++) {
        float4 pv = *(float4*)&qT[kk * 64 + (((ic4 ^ (kk & 15)) << 2))];
        float p[4] = {pv.x, pv.y, pv.z, pv.w};
        float4 vv = *(float4*)&vs[kk * 64 + j0];
        float vb[4] = {vv.x, vv.y, vv.z, vv.w};
#pragma unroll
        for (int ri = 0; ri < 4; ri++)
#pragma unroll
            for (int rd = 0; rd < 4; rd++) c4[ri][rd] += p[ri] * vb[rd];
    }
    __syncthreads();

    // ---- swizzled ctx^T[d][i]: addr = d*64 + ((ic4 ^ (d&15))<<2) + ri ----
#pragma unroll
    for (int rd = 0; rd < 4; rd++) {
        int d = j0 + rd;
        int base = d * 64 + (((ic4 ^ (d & 15)) << 2));
#pragma unroll
        for (int ri = 0; ri < 4; ri++)
            kT[base + ri] = c4[ri][rd];
    }
    __syncthreads();

    // ---- coalesced store to (B, C, H, W), de-swizzling reads ----
    for (int e = t; e < 4096; e += 256) {
        int d  = e >> 6;
        int ii = e & 63;
        int ni = ((xw << 3) + (ii >> 3)) * WW2 + (yw << 3) + (ii & 7);
        float v = kT[d * 64 + ((((ii >> 2) ^ (d & 15)) << 2) | (ii & 3))];
        xvec[((size_t)(b * CC + head * 64 + d)) * NN + ni] = v;
    }
}

// ---------------- fold fc2+bit into a single 2C vector ----------------
__global__ void fuse_fw(const float* __restrict__ fc2w,
                        const float* __restrict__ fc2b,
                        const float* __restrict__ bitw,
                        const float* __restrict__ bitb, int sel)
{
    int k = blockIdx.x * blockDim.x + threadIdx.x;
    if (k < HC) {
        float s = 0.f;
        for (int c = 0; c < CC; c++) s += fc2w[(size_t)k * CC + c] * bitw[c];
        d_fw[sel][k] = s;
    }
    if (k == 0) {
        float s = 0.f;
        for (int c = 0; c < CC; c++) s += fc2b[c] * bitw[c];
        d_fb[sel] = s + bitb[0];
    }
}

// ---------------- InstanceNorm stats over h (fc1 bias cancels) -----------
__global__ __launch_bounds__(256) void inorm_stats(int sel)
{
    const int hoff = sel ? OFF_WH : OFF_GH;
    const int b  = blockIdx.x;
    const int c0 = blockIdx.y * 32;
    const int cl = threadIdx.x & 31;
    const int rr = threadIdx.x >> 5;

    const float* base = d_big + (size_t)b * NN * OSTR + hoff + c0 + cl;
    float s = 0.f, s2 = 0.f;
    for (int n = rr; n < NN; n += 8) {
        float v = base[(size_t)n * OSTR];
        s += v; s2 += v * v;
    }
    __shared__ float ss[8][32], ss2[8][32];
    ss[rr][cl] = s; ss2[rr][cl] = s2;
    __syncthreads();
    if (threadIdx.x < 32) {
        float a = 0.f, a2 = 0.f;
#pragma unroll
        for (int r = 0; r < 8; r++) { a += ss[r][threadIdx.x]; a2 += ss2[r][threadIdx.x]; }
        float m   = a * (1.0f / NN);
        float var = a2 * (1.0f / NN) - m * m;
        d_mu[sel][b * HC + c0 + threadIdx.x]   = m;
        d_rstd[sel][b * HC + c0 + threadIdx.x] = rsqrtf(var + 1e-5f);
    }
}

// ---------------- norm + gelu + fused fc2/bit GEMV -> x_bit ----------------
__global__ __launch_bounds__(256) void mlp_bit(int sel)
{
    const int hoff = sel ? OFF_WH : OFF_GH;
    float* xbit    = sel ? d_xbit_w : d_xbit_g;

    __shared__ float smu[HC], srs[HC], sfw[HC];
    const int t  = threadIdx.x;
    const int r0 = blockIdx.x * 8;
    const int b  = r0 >> 14;

    smu[t]       = d_mu[sel][b * HC + t];
    smu[t + 256] = d_mu[sel][b * HC + t + 256];
    srs[t]       = d_rstd[sel][b * HC + t];
    srs[t + 256] = d_rstd[sel][b * HC + t + 256];
    sfw[t]       = d_fw[sel][t];
    sfw[t + 256] = d_fw[sel][t + 256];
    __syncthreads();

    const float fb = d_fb[sel];
    const int w = t >> 5, lane = t & 31;
    const int r = r0 + w;
    const float* hr = d_big + (size_t)r * OSTR + hoff;

    float acc = 0.f;
#pragma unroll
    for (int ii = 0; ii < 16; ii++) {
        int k   = lane + (ii << 5);
        float v = (hr[k] - smu[k]) * srs[k];
        float g = 0.5f * v * (1.0f + erff(v * 0.70710678118f));
        acc += g * sfw[k];
    }
#pragma unroll
    for (int off = 16; off > 0; off >>= 1)
        acc += __shfl_xor_sync(0xffffffffu, acc, off);
    if (lane == 0) xbit[r] = fmaxf(acc + fb, 0.0f);
}

// ---------------- final combine ----------------
__global__ __launch_bounds__(256) void combine_kernel(
    const float* __restrict__ x, float* __restrict__ out)
{
    size_t idx = (size_t)blockIdx.x * 256 + threadIdx.x;
    size_t e   = idx * 4;
    int n      = (int)(e & (NN - 1));
    size_t bc  = e >> 14;
    int b      = (int)(bc >> 8);

    float4 x4 = *(const float4*)&x[e];
    float4 vg = *(const float4*)&d_xvec_g[e];
    float4 vw = *(const float4*)&d_xvec_w[e];
    float4 bg = *(const float4*)&d_xbit_g[(size_t)b * NN + n];
    float4 bw = *(const float4*)&d_xbit_w[(size_t)b * NN + n];

    float4 o;
    {
        float wv = bw.x * vw.x; float sg = 1.0f / (1.0f + __expf(-wv));
        o.x = x4.x * sg + (bg.x * vg.x) * (1.0f - sg);
    }
    {
        float wv = bw.y * vw.y; float sg = 1.0f / (1.0f + __expf(-wv));
        o.y = x4.y * sg + (bg.y * vg.y) * (1.0f - sg);
    }
    {
        float wv = bw.z * vw.z; float sg = 1.0f / (1.0f + __expf(-wv));
        o.z = x4.z * sg + (bg.z * vg.z) * (1.0f - sg);
    }
    {
        float wv = bw.w * vw.w; float sg = 1.0f / (1.0f + __expf(-wv));
        o.w = x4.w * sg + (bg.w * vg.w) * (1.0f - sg);
    }
    *(float4*)&out[e] = o;
}

// ---------------- launch ----------------
extern "C" void kernel_launch(void* const* d_in, const int* in_sizes, int n_in,
                              void* d_out, int out_size)
{
    const float* x       = (const float*)d_in[0];
    const float* g_qkv   = (const float*)d_in[1];
    const float* g_fc1_w = (const float*)d_in[2];
    // d_in[3] = g_fc1_b  (provably cancelled by instance norm)
    const float* g_fc2_w = (const float*)d_in[4];
    const float* g_fc2_b = (const float*)d_in[5];
    const float* g_bit_w = (const float*)d_in[6];
    const float* g_bit_b = (const float*)d_in[7];
    const float* w_qkv   = (const float*)d_in[8];
    const float* w_fc1_w = (const float*)d_in[9];
    // d_in[10] = w_fc1_b (cancelled)
    const float* w_fc2_w = (const float*)d_in[11];
    const float* w_fc2_b = (const float*)d_in[12];
    const float* w_bit_w = (const float*)d_in[13];
    const float* w_bit_b = (const float*)d_in[14];
    float* out = (float*)d_out;

    cudaFuncSetAttribute(gemm_f16, cudaFuncAttributeMaxDynamicSharedMemorySize,
                         GEMM_SMEM);

    // prep: fp16 conversions of activations + packed weights
    split_x<<<((size_t)BB * CC * NN / 4) / 256, 256>>>(x);
    pack_w<<<(CC * OSTR) / 256, 256>>>(g_qkv, g_fc1_w, w_qkv, w_fc1_w);

    // one fused tensor-core GEMM (fp16 in, fp32 accum): [BN,256] @ [256,2560]
    gemm_f16<<<dim3(OSTR / 256, BN / 128), 512, GEMM_SMEM>>>();

    // windowed attention (2048 windows * 4 heads per branch)
    attn_kernel<<<8192, 256>>>(0);
    attn_kernel<<<8192, 256>>>(1);

    // folded fc2+bit weights
    fuse_fw<<<2, 256>>>(g_fc2_w, g_fc2_b, g_bit_w, g_bit_b, 0);
    fuse_fw<<<2, 256>>>(w_fc2_w, w_fc2_b, w_bit_w, w_bit_b, 1);

    // instance-norm stats + bit branch
    inorm_stats<<<dim3(BB, 16), 256>>>(0);
    inorm_stats<<<dim3(BB, 16), 256>>>(1);
    mlp_bit<<<BN / 8, 256>>>(0);
    mlp_bit<<<BN / 8, 256>>>(1);

    // final blend
    combine_kernel<<<((size_t)BB * CC * NN / 4) / 256, 256>>>(x, out);
}

// round 11
// speedup vs baseline: 2.9083x; 1.1610x over previous
#include <cuda_runtime.h>
#include <cuda_fp16.h>
#include <cuda_bf16.h>
#include <mma.h>
#include <cstddef>
#include <cstdint>
#include <math.h>

using namespace nvcuda;

// Problem constants
#define BB 8
#define CC 256
#define HH 128
#define WW2 128
#define NN 16384           // H*W
#define BN 131072          // B*N
#define QKVC 768           // 3C
#define HC 512             // 2C
#define OSTR 2560          // fused GEMM output columns

// column offsets inside the fused output  [gqkv 0..768 | gh 768..1280 | wqkv 1280..2048 | wh 2048..2560]
#define OFF_GQKV 0
#define OFF_GH   768
#define OFF_WQKV 1280
#define OFF_WH   2048

// ---------------- scratch (device globals; no allocation) ----------------
__device__ float d_big[(size_t)BN * OSTR];   // fused GEMM output (1.34 GB)
__device__ __half d_xh[(size_t)BB * CC * NN];
__device__ __half d_wh[(size_t)CC * OSTR];
__device__ float d_xbit_g[BN];
__device__ float d_xbit_w[BN];
__device__ float d_mu[2][BB * HC];
__device__ float d_rstd[2][BB * HC];
__device__ float d_fw[2][HC];
__device__ float d_fb[2];

// ======================= helpers ============================
__device__ __forceinline__ uint32_t smem_u32(const void* p) {
    uint32_t a;
    asm("{ .reg .u64 t; cvta.to.shared.u64 t, %1; cvt.u32.u64 %0, t; }"
        : "=r"(a) : "l"(p));
    return a;
}
__device__ __forceinline__ void cp16(uint32_t dst, const void* src) {
    asm volatile("cp.async.cg.shared.global [%0], [%1], 16;"
                 :: "r"(dst), "l"(src));
}

// ================== convert x -> fp16, same layout ==================
__global__ __launch_bounds__(256) void split_x(const float* __restrict__ x)
{
    size_t i = ((size_t)blockIdx.x * 256 + threadIdx.x) * 4;
    float4 v = *(const float4*)&x[i];
    __half h[4];
    h[0] = __float2half_rn(v.x);
    h[1] = __float2half_rn(v.y);
    h[2] = __float2half_rn(v.z);
    h[3] = __float2half_rn(v.w);
    *(uint2*)&d_xh[i] = *(uint2*)h;
}

// ====== pack weights into [c][2560] fp16 (fused column space) ========
__global__ __launch_bounds__(256) void pack_w(
    const float* __restrict__ gq, const float* __restrict__ gf,
    const float* __restrict__ wq, const float* __restrict__ wf)
{
    int idx = blockIdx.x * 256 + threadIdx.x;   // 0 .. CC*OSTR-1
    int c = idx / OSTR;
    int j = idx % OSTR;
    const float* src; int jj; int ncol;
    if (j < 768)       { src = gq; jj = j;        ncol = QKVC; }
    else if (j < 1280) { src = gf; jj = j - 768;  ncol = HC;   }
    else if (j < 2048) { src = wq; jj = j - 1280; ncol = QKVC; }
    else               { src = wf; jj = j - 2048; ncol = HC;   }
    d_wh[idx] = __float2half_rn(src[(size_t)c * ncol + jj]);
}

// ============== WMMA fp16 GEMM: d_big = A @ W (fp32 accum) ============
#define BKT 32
#define LDAs 136
#define LDBs 264
#define ASTG (BKT * LDAs)
#define BSTG (BKT * LDBs)
#define STGE (ASTG + BSTG)
#define NSTG 3
#define GEMM_SMEM (NSTG * STGE * 2)

__global__ __launch_bounds__(512, 1) void gemm_f16()
{
    extern __shared__ __half sm[];
    const uint32_t smb = smem_u32(sm);
    const int t   = threadIdx.x;
    const int wid = t >> 5;

    const int nt = blockIdx.x;
    const int mt = blockIdx.y;
    const int j0 = nt * 256;
    const int r0 = mt * 128;
    const int b  = mt >> 7;
    const int n0 = r0 & (NN - 1);

    const __half* ax = d_xh + (size_t)b * CC * NN + n0;
    const __half* bw = d_wh + j0;

    const int wm = (wid & 3) * 32;
    const int wn = (wid >> 2) * 64;

    wmma::fragment<wmma::accumulator, 16, 16, 16, float> acc[2][4];
#pragma unroll
    for (int i = 0; i < 2; i++)
#pragma unroll
        for (int j = 0; j < 4; j++) wmma::fill_fragment(acc[i][j], 0.0f);

    auto load_stage = [&](int s, int c0) {
        const uint32_t sbase = smb + (uint32_t)(s * STGE) * 2;
#pragma unroll
        for (int i = 0; i < 3; i++) {
            int q = t + i * 512;
            if (q < 512) {
                int k = q >> 4, c8 = (q & 15) << 3;
                cp16(sbase + (uint32_t)(k * LDAs + c8) * 2,
                     ax + (size_t)(c0 + k) * NN + c8);
            } else {
                int q2 = q - 512;
                int k = q2 >> 5, j8 = (q2 & 31) << 3;
                cp16(sbase + (uint32_t)(ASTG + k * LDBs + j8) * 2,
                     bw + (size_t)(c0 + k) * OSTR + j8);
            }
        }
        asm volatile("cp.async.commit_group;");
    };

    load_stage(0, 0);
    load_stage(1, BKT);

#pragma unroll 1
    for (int kt = 0; kt < 8; kt++) {
        if (kt + 2 < 8) {
            load_stage((kt + 2) % 3, (kt + 2) * BKT);
            asm volatile("cp.async.wait_group 2;");
        } else if (kt + 1 < 8) {
            asm volatile("cp.async.wait_group 1;");
        } else {
            asm volatile("cp.async.wait_group 0;");
        }
        __syncthreads();

        const __half* st = sm + (size_t)(kt % 3) * STGE;
        const __half* As = st;
        const __half* Bs = st + ASTG;

#pragma unroll
        for (int ks = 0; ks < 2; ks++) {
            wmma::fragment<wmma::matrix_a, 16, 16, 16, __half,
                           wmma::col_major> af[2];
            wmma::load_matrix_sync(af[0], As + (ks * 16) * LDAs + wm, LDAs);
            wmma::load_matrix_sync(af[1], As + (ks * 16) * LDAs + wm + 16, LDAs);
#pragma unroll
            for (int j = 0; j < 4; j++) {
                wmma::fragment<wmma::matrix_b, 16, 16, 16, __half,
                               wmma::row_major> bf;
                wmma::load_matrix_sync(bf, Bs + (ks * 16) * LDBs + wn + j * 16, LDBs);
                wmma::mma_sync(acc[0][j], af[0], bf, acc[0][j]);
                wmma::mma_sync(acc[1][j], af[1], bf, acc[1][j]);
            }
        }
        __syncthreads();
    }

#pragma unroll
    for (int i = 0; i < 2; i++)
#pragma unroll
        for (int j = 0; j < 4; j++)
            wmma::store_matrix_sync(
                d_big + (size_t)(r0 + wm + i * 16) * OSTR + j0 + wn + j * 16,
                acc[i][j], OSTR, wmma::mem_row_major);
}

// ======== fused tensor-core attention (both branches) + final blend ========
// One block = (window, head). 256 threads (8 warps).
// smem layout (halves / floats):
//   Qh[64][72]h, Kh[64][72]h, Vh[64][72]h, Ph[64][72]h,
//   Ssm[64][68]f (S, then ctx_w), Cg[64][68]f (ctx_g), sbg[64]f, sbw[64]f
#define LDH 72
#define LDS4 68
#define A_QH   0
#define A_KH   9216
#define A_VH   18432
#define A_PH   27648
#define A_SS   36864
#define A_CG   54272
#define A_BG   71680
#define A_BW   71936
#define ATTN_SMEM 72192

// one branch: QKV load -> S=QK^T -> softmax -> ctx=P*V -> ctx into dst
__device__ __forceinline__ void attn_branch(
    char* smem, const float* __restrict__ qkvbase, float* __restrict__ cdst,
    int t, int wid)
{
    __half* Qh = (__half*)(smem + A_QH);
    __half* Kh = (__half*)(smem + A_KH);
    __half* Vh = (__half*)(smem + A_VH);
    __half* Ph = (__half*)(smem + A_PH);
    float*  Ss = (float*)(smem + A_SS);

    // ---- load QKV (fp32 global -> fp16 smem, untransposed) ----
    {
        const int i  = t >> 2;
        const int d0 = (t & 3) << 4;
        const float* rp = qkvbase + (size_t)i * 0;   // placeholder
        (void)rp;
#pragma unroll
        for (int u = 0; u < 4; u++) {
            int d = d0 + u * 4;
            const float* row = qkvbase;   // per-token pointer set below
            (void)row;
        }
    }
    // (real load done by caller-specific code below via macro-free inline)
    (void)Qh; (void)Kh; (void)Vh; (void)Ph; (void)Ss; (void)cdst; (void)wid;
}

__global__ __launch_bounds__(256) void attn_combine(
    const float* __restrict__ x, float* __restrict__ out)
{
    extern __shared__ char smem[];
    __half* Qh = (__half*)(smem + A_QH);
    __half* Kh = (__half*)(smem + A_KH);
    __half* Vh = (__half*)(smem + A_VH);
    __half* Ph = (__half*)(smem + A_PH);
    float*  Ss = (float*)(smem + A_SS);
    float*  Cg = (float*)(smem + A_CG);
    float*  sbg = (float*)(smem + A_BG);
    float*  sbw = (float*)(smem + A_BW);

    const int t    = threadIdx.x;
    const int wid  = t >> 5;
    const int bx   = blockIdx.x;
    const int win  = bx >> 2;
    const int head = bx & 3;
    const int b    = win >> 8;
    const int wib  = win & 255;
    const int xw   = wib >> 4;
    const int yw   = wib & 15;

    const int li  = t >> 2;            // token 0..63 for loads
    const int ld0 = (t & 3) << 4;      // d-group
    const int lni = ((xw << 3) + (li >> 3)) * WW2 + (yw << 3) + (li & 7);

    // preload x_bit for this window's 64 tokens
    if (t < 64) {
        int ni = ((xw << 3) + (t >> 3)) * WW2 + (yw << 3) + (t & 7);
        sbg[t] = d_xbit_g[(size_t)b * NN + ni];
    } else if (t < 128) {
        int tt = t - 64;
        int ni = ((xw << 3) + (tt >> 3)) * WW2 + (yw << 3) + (tt & 7);
        sbw[tt] = d_xbit_w[(size_t)b * NN + ni];
    }

    const int wi = (wid >> 1) * 16;    // warp row  (0,16,32,48)
    const int wj = (wid & 1) * 32;     // warp col  (0,32)

#pragma unroll
    for (int br = 0; br < 2; br++) {
        const int qoff = (br ? OFF_WQKV : OFF_GQKV) + head * 64;
        float* cdst = br ? Ss : Cg;    // branch w ctx reuses S buffer

        // ---- load QKV ----
        {
            const float* rp = d_big + (size_t)(b * NN + lni) * OSTR + qoff;
#pragma unroll
            for (int u = 0; u < 4; u++) {
                int d = ld0 + u * 4;
                float4 qv = *(const float4*)&rp[d];
                __half hq[4] = {
                    __float2half_rn(qv.x * 0.125f), __float2half_rn(qv.y * 0.125f),
                    __float2half_rn(qv.z * 0.125f), __float2half_rn(qv.w * 0.125f)};
                *(uint2*)&Qh[li * LDH + d] = *(uint2*)hq;
                float4 kv = *(const float4*)&rp[256 + d];
                __half hk[4] = {
                    __float2half_rn(kv.x), __float2half_rn(kv.y),
                    __float2half_rn(kv.z), __float2half_rn(kv.w)};
                *(uint2*)&Kh[li * LDH + d] = *(uint2*)hk;
                float4 vv = *(const float4*)&rp[512 + d];
                __half hv[4] = {
                    __float2half_rn(vv.x), __float2half_rn(vv.y),
                    __float2half_rn(vv.z), __float2half_rn(vv.w)};
                *(uint2*)&Vh[li * LDH + d] = *(uint2*)hv;
            }
        }
        __syncthreads();

        // ---- S = Q K^T  (warp: 16x32 region) ----
        {
            wmma::fragment<wmma::accumulator, 16, 16, 16, float> c0, c1;
            wmma::fill_fragment(c0, 0.0f);
            wmma::fill_fragment(c1, 0.0f);
#pragma unroll
            for (int k0 = 0; k0 < 64; k0 += 16) {
                wmma::fragment<wmma::matrix_a, 16, 16, 16, __half,
                               wmma::row_major> af;
                wmma::fragment<wmma::matrix_b, 16, 16, 16, __half,
                               wmma::col_major> bf0, bf1;
                wmma::load_matrix_sync(af,  Qh + wi * LDH + k0, LDH);
                wmma::load_matrix_sync(bf0, Kh + wj * LDH + k0, LDH);
                wmma::load_matrix_sync(bf1, Kh + (wj + 16) * LDH + k0, LDH);
                wmma::mma_sync(c0, af, bf0, c0);
                wmma::mma_sync(c1, af, bf1, c1);
            }
            wmma::store_matrix_sync(Ss + wi * LDS4 + wj,      c0, LDS4,
                                    wmma::mem_row_major);
            wmma::store_matrix_sync(Ss + wi * LDS4 + wj + 16, c1, LDS4,
                                    wmma::mem_row_major);
        }
        __syncthreads();

        // ---- softmax: 4 lanes per row, 16 cols each ----
        {
            const int row = t >> 2;
            const int qq  = t & 3;
            float* sr = Ss + row * LDS4 + qq * 16;
            float4 v0 = *(float4*)&sr[0];
            float4 v1 = *(float4*)&sr[4];
            float4 v2 = *(float4*)&sr[8];
            float4 v3 = *(float4*)&sr[12];
            float m = fmaxf(fmaxf(fmaxf(v0.x, v0.y), fmaxf(v0.z, v0.w)),
                     fmaxf(fmaxf(fmaxf(v1.x, v1.y), fmaxf(v1.z, v1.w)),
                     fmaxf(fmaxf(fmaxf(v2.x, v2.y), fmaxf(v2.z, v2.w)),
                           fmaxf(fmaxf(v3.x, v3.y), fmaxf(v3.z, v3.w)))));
            m = fmaxf(m, __shfl_xor_sync(0xffffffffu, m, 1));
            m = fmaxf(m, __shfl_xor_sync(0xffffffffu, m, 2));
            float e[16];
            e[0] = __expf(v0.x - m); e[1] = __expf(v0.y - m);
            e[2] = __expf(v0.z - m); e[3] = __expf(v0.w - m);
            e[4] = __expf(v1.x - m); e[5] = __expf(v1.y - m);
            e[6] = __expf(v1.z - m); e[7] = __expf(v1.w - m);
            e[8] = __expf(v2.x - m); e[9] = __expf(v2.y - m);
            e[10] = __expf(v2.z - m); e[11] = __expf(v2.w - m);
            e[12] = __expf(v3.x - m); e[13] = __expf(v3.y - m);
            e[14] = __expf(v3.z - m); e[15] = __expf(v3.w - m);
            float sum = 0.f;
#pragma unroll
            for (int u = 0; u < 16; u++) sum += e[u];
            sum += __shfl_xor_sync(0xffffffffu, sum, 1);
            sum += __shfl_xor_sync(0xffffffffu, sum, 2);
            float inv = 1.0f / sum;
            __half* pr = Ph + row * LDH + qq * 16;
#pragma unroll
            for (int u = 0; u < 4; u++) {
                __half hp[4] = {
                    __float2half_rn(e[u * 4 + 0] * inv),
                    __float2half_rn(e[u * 4 + 1] * inv),
                    __float2half_rn(e[u * 4 + 2] * inv),
                    __float2half_rn(e[u * 4 + 3] * inv)};
                *(uint2*)&pr[u * 4] = *(uint2*)hp;
            }
        }
        __syncthreads();

        // ---- ctx = P V  (warp: 16x32 region) ----
        {
            wmma::fragment<wmma::accumulator, 16, 16, 16, float> c0, c1;
            wmma::fill_fragment(c0, 0.0f);
            wmma::fill_fragment(c1, 0.0f);
#pragma unroll
            for (int k0 = 0; k0 < 64; k0 += 16) {
                wmma::fragment<wmma::matrix_a, 16, 16, 16, __half,
                               wmma::row_major> af;
                wmma::fragment<wmma::matrix_b, 16, 16, 16, __half,
                               wmma::row_major> bf0, bf1;
                wmma::load_matrix_sync(af,  Ph + wi * LDH + k0, LDH);
                wmma::load_matrix_sync(bf0, Vh + k0 * LDH + wj, LDH);
                wmma::load_matrix_sync(bf1, Vh + k0 * LDH + wj + 16, LDH);
                wmma::mma_sync(c0, af, bf0, c0);
                wmma::mma_sync(c1, af, bf1, c1);
            }
            wmma::store_matrix_sync(cdst + wi * LDS4 + wj,      c0, LDS4,
                                    wmma::mem_row_major);
            wmma::store_matrix_sync(cdst + wi * LDS4 + wj + 16, c1, LDS4,
                                    wmma::mem_row_major);
        }
        __syncthreads();
    }

    // ---- final blend: out = x*sg + (bg*vg)*(1-sg), sg = sigmoid(bw*vw) ----
    for (int e = t; e < 4096; e += 256) {
        int d  = e >> 6;
        int ii = e & 63;
        int ni = ((xw << 3) + (ii >> 3)) * WW2 + (yw << 3) + (ii & 7);
        size_t gidx = ((size_t)(b * CC + head * 64 + d)) * NN + ni;
        float vg = Cg[ii * LDS4 + d];
        float vw = Ss[ii * LDS4 + d];
        float wv = sbw[ii] * vw;
        float sg = 1.0f / (1.0f + __expf(-wv));
        out[gidx] = x[gidx] * sg + (sbg[ii] * vg) * (1.0f - sg);
    }
}

// ---------------- fold fc2+bit into a single 2C vector ----------------
__global__ void fuse_fw(const float* __restrict__ fc2w,
                        const float* __restrict__ fc2b,
                        const float* __restrict__ bitw,
                        const float* __restrict__ bitb, int sel)
{
    int k = blockIdx.x * blockDim.x + threadIdx.x;
    if (k < HC) {
        float s = 0.f;
        for (int c = 0; c < CC; c++) s += fc2w[(size_t)k * CC + c] * bitw[c];
        d_fw[sel][k] = s;
    }
    if (k == 0) {
        float s = 0.f;
        for (int c = 0; c < CC; c++) s += fc2b[c] * bitw[c];
        d_fb[sel] = s + bitb[0];
    }
}

// ---------------- InstanceNorm stats over h (fc1 bias cancels) -----------
__global__ __launch_bounds__(256) void inorm_stats(int sel)
{
    const int hoff = sel ? OFF_WH : OFF_GH;
    const int b  = blockIdx.x;
    const int c0 = blockIdx.y * 32;
    const int cl = threadIdx.x & 31;
    const int rr = threadIdx.x >> 5;

    const float* base = d_big + (size_t)b * NN * OSTR + hoff + c0 + cl;
    float s = 0.f, s2 = 0.f;
    for (int n = rr; n < NN; n += 8) {
        float v = base[(size_t)n * OSTR];
        s += v; s2 += v * v;
    }
    __shared__ float ss[8][32], ss2[8][32];
    ss[rr][cl] = s; ss2[rr][cl] = s2;
    __syncthreads();
    if (threadIdx.x < 32) {
        float a = 0.f, a2 = 0.f;
#pragma unroll
        for (int r = 0; r < 8; r++) { a += ss[r][threadIdx.x]; a2 += ss2[r][threadIdx.x]; }
        float m   = a * (1.0f / NN);
        float var = a2 * (1.0f / NN) - m * m;
        d_mu[sel][b * HC + c0 + threadIdx.x]   = m;
        d_rstd[sel][b * HC + c0 + threadIdx.x] = rsqrtf(var + 1e-5f);
    }
}

// ---------------- norm + gelu + fused fc2/bit GEMV -> x_bit ----------------
__global__ __launch_bounds__(256) void mlp_bit(int sel)
{
    const int hoff = sel ? OFF_WH : OFF_GH;
    float* xbit    = sel ? d_xbit_w : d_xbit_g;

    __shared__ float smu[HC], srs[HC], sfw[HC];
    const int t  = threadIdx.x;
    const int r0 = blockIdx.x * 8;
    const int b  = r0 >> 14;

    smu[t]       = d_mu[sel][b * HC + t];
    smu[t + 256] = d_mu[sel][b * HC + t + 256];
    srs[t]       = d_rstd[sel][b * HC + t];
    srs[t + 256] = d_rstd[sel][b * HC + t + 256];
    sfw[t]       = d_fw[sel][t];
    sfw[t + 256] = d_fw[sel][t + 256];
    __syncthreads();

    const float fb = d_fb[sel];
    const int w = t >> 5, lane = t & 31;
    const int r = r0 + w;
    const float* hr = d_big + (size_t)r * OSTR + hoff;

    float acc = 0.f;
#pragma unroll
    for (int ii = 0; ii < 16; ii++) {
        int k   = lane + (ii << 5);
        float v = (hr[k] - smu[k]) * srs[k];
        float g = 0.5f * v * (1.0f + erff(v * 0.70710678118f));
        acc += g * sfw[k];
    }
#pragma unroll
    for (int off = 16; off > 0; off >>= 1)
        acc += __shfl_xor_sync(0xffffffffu, acc, off);
    if (lane == 0) xbit[r] = fmaxf(acc + fb, 0.0f);
}

// ---------------- launch ----------------
extern "C" void kernel_launch(void* const* d_in, const int* in_sizes, int n_in,
                              void* d_out, int out_size)
{
    const float* x       = (const float*)d_in[0];
    const float* g_qkv   = (const float*)d_in[1];
    const float* g_fc1_w = (const float*)d_in[2];
    const float* g_fc2_w = (const float*)d_in[4];
    const float* g_fc2_b = (const float*)d_in[5];
    const float* g_bit_w = (const float*)d_in[6];
    const float* g_bit_b = (const float*)d_in[7];
    const float* w_qkv   = (const float*)d_in[8];
    const float* w_fc1_w = (const float*)d_in[9];
    const float* w_fc2_w = (const float*)d_in[11];
    const float* w_fc2_b = (const float*)d_in[12];
    const float* w_bit_w = (const float*)d_in[13];
    const float* w_bit_b = (const float*)d_in[14];
    float* out = (float*)d_out;

    cudaFuncSetAttribute(gemm_f16, cudaFuncAttributeMaxDynamicSharedMemorySize,
                         GEMM_SMEM);
    cudaFuncSetAttribute(attn_combine, cudaFuncAttributeMaxDynamicSharedMemorySize,
                         ATTN_SMEM);

    // prep: fp16 conversions of activations + packed weights
    split_x<<<((size_t)BB * CC * NN / 4) / 256, 256>>>(x);
    pack_w<<<(CC * OSTR) / 256, 256>>>(g_qkv, g_fc1_w, w_qkv, w_fc1_w);

    // one fused tensor-core GEMM (fp16 in, fp32 accum): [BN,256] @ [256,2560]
    gemm_f16<<<dim3(OSTR / 256, BN / 128), 512, GEMM_SMEM>>>();

    // bit branch first (attn_combine consumes x_bit)
    fuse_fw<<<2, 256>>>(g_fc2_w, g_fc2_b, g_bit_w, g_bit_b, 0);
    fuse_fw<<<2, 256>>>(w_fc2_w, w_fc2_b, w_bit_w, w_bit_b, 1);
    inorm_stats<<<dim3(BB, 16), 256>>>(0);
    inorm_stats<<<dim3(BB, 16), 256>>>(1);
    mlp_bit<<<BN / 8, 256>>>(0);
    mlp_bit<<<BN / 8, 256>>>(1);

    // fused tensor-core attention (both branches) + final blend
    attn_combine<<<8192, 256, ATTN_SMEM>>>(x, out);
}